// round 7
// baseline (speedup 1.0000x reference)
#include <cuda_runtime.h>

// EthanolSNN: 3-layer LIF SNN inference. T=256, B=8192, D=64, H1=28, H2=14.
// Output mem3 [T, B, 1] fp32.
//
// Numerics (must stay bit-identical to the round-5 passing kernel):
//  - every dot product: single serial ascending-index FMA chain per neuron
//  - bias added as separate rounded add after the chain
//  - LIF: RN(RN(RN(b*m)+cur)-reset), reset subtract via exact-product fma
//  - threshold m>1 == (m-1)>0 in fp32
//
// Parallelization (new this round): 4 threads per element, split by NEURON
// groups (h1: 7 per thread; h2: 4/4/3/3). Each neuron's chain lives wholly on
// one thread -> bit-identical math, 2x the warps for latency hiding.
// Spikes all-gathered across the 4-thread group with intra-warp shuffles.

typedef unsigned long long ull_t;

#define TT 256
#define BB 8192
#define DD 64
#define HH1 28
#define HH2 14

__device__ __forceinline__ ull_t pk2(float lo, float hi) {
    ull_t r;
    asm("mov.b64 %0, {%1, %2};" : "=l"(r) : "f"(lo), "f"(hi));
    return r;
}
__device__ __forceinline__ void upk2(ull_t v, float& lo, float& hi) {
    asm("mov.b64 {%0, %1}, %2;" : "=f"(lo), "=f"(hi) : "l"(v));
}
__device__ __forceinline__ ull_t fma2(ull_t a, ull_t b, ull_t c) {
    ull_t d;
    asm("fma.rn.f32x2 %0, %1, %2, %3;" : "=l"(d) : "l"(a), "l"(b), "l"(c));
    return d;
}
__device__ __forceinline__ ull_t add2(ull_t a, ull_t b) {
    ull_t d;
    asm("add.rn.f32x2 %0, %1, %2;" : "=l"(d) : "l"(a), "l"(b));
    return d;
}
__device__ __forceinline__ ull_t mul2(ull_t a, ull_t b) {
    ull_t d;
    asm("mul.rn.f32x2 %0, %1, %2;" : "=l"(d) : "l"(a), "l"(b));
    return d;
}
__device__ __forceinline__ float getlane(ull_t v, int hi_sel) {
    float lo, hi;
    upk2(v, lo, hi);
    return hi_sel ? hi : lo;
}

__global__ void __launch_bounds__(64, 1)
snn_fused_kernel(const float* __restrict__ x,
                 const float* __restrict__ W1, const float* __restrict__ b1,
                 const float* __restrict__ W2, const float* __restrict__ b2,
                 const float* __restrict__ W3, const float* __restrict__ b3,
                 float* __restrict__ out)
{
    // w1r[k][4q+j] = {W1[7q+2j][k], W1[7q+2j+1][k]} (j=3 hi lane = pad 0); row = 16 ull = 128B
    // w2r[i][2q+j] = packed pair of thread q's h2 neurons at column i;   row = 8 ull = 64B
    __shared__ __align__(16) ull_t w1r[DD * 16];
    __shared__ __align__(16) ull_t w2r[HH1 * 8];
    __shared__ ull_t b1p[16];
    __shared__ ull_t b2p[8];
    __shared__ float w3s[14];
    __shared__ float b3s;

    const int tid  = threadIdx.x;
    const int lane = tid & 31;
    const int q    = lane & 3;            // neuron-group owner (0..3)
    const int p    = lane >> 2;           // element slot within warp (0..7)
    const int e    = blockIdx.x * 16 + (tid >> 5) * 8 + p;

    // h2 neuron split: 4/4/3/3
    // base2 = {0,4,8,11}, end2 = {4,8,11,14}

    // ---- pack weights into shared ----
    for (int idx = tid; idx < DD * 16; idx += 64) {
        int k = idx >> 4, s = idx & 15, qq = s >> 2, j = s & 3;
        int n0 = 7 * qq + 2 * j;
        float lo = (2 * j     < 7) ? W1[n0       * DD + k] : 0.f;
        float hi = (2 * j + 1 < 7) ? W1[(n0 + 1) * DD + k] : 0.f;
        w1r[idx] = pk2(lo, hi);
    }
    for (int idx = tid; idx < HH1 * 8; idx += 64) {
        int i = idx >> 3, s = idx & 7, qq = s >> 1, j = s & 1;
        int base2 = (qq == 0) ? 0 : (qq == 1) ? 4 : (qq == 2) ? 8 : 11;
        int end2  = (qq == 0) ? 4 : (qq == 1) ? 8 : (qq == 2) ? 11 : 14;
        int n0 = base2 + 2 * j;
        float lo = (n0     < end2) ? W2[n0       * HH1 + i] : 0.f;
        float hi = (n0 + 1 < end2) ? W2[(n0 + 1) * HH1 + i] : 0.f;
        w2r[idx] = pk2(lo, hi);
    }
    if (tid < 16) {
        int qq = tid >> 2, j = tid & 3;
        int n0 = 7 * qq + 2 * j;
        float lo = (2 * j     < 7) ? b1[n0]     : 0.f;
        float hi = (2 * j + 1 < 7) ? b1[n0 + 1] : 0.f;
        b1p[tid] = pk2(lo, hi);
    }
    if (tid < 8) {
        int qq = tid >> 1, j = tid & 1;
        int base2 = (qq == 0) ? 0 : (qq == 1) ? 4 : (qq == 2) ? 8 : 11;
        int end2  = (qq == 0) ? 4 : (qq == 1) ? 8 : (qq == 2) ? 11 : 14;
        int n0 = base2 + 2 * j;
        float lo = (n0     < end2) ? b2[n0]     : 0.f;
        float hi = (n0 + 1 < end2) ? b2[n0 + 1] : 0.f;
        b2p[tid] = pk2(lo, hi);
    }
    if (tid < 14) w3s[tid] = W3[tid];
    if (tid == 0) b3s = b3[0];
    __syncthreads();

    ull_t b1own[4], b2own[2];
    #pragma unroll
    for (int j = 0; j < 4; j++) b1own[j] = b1p[q * 4 + j];
    #pragma unroll
    for (int j = 0; j < 2; j++) b2own[j] = b2p[q * 2 + j];

    const ull_t BETA2 = pk2(0.9f, 0.9f);
    const ull_t NEG2  = pk2(-1.0f, -1.0f);

    ull_t m1v[4], m2v[2];
    #pragma unroll
    for (int j = 0; j < 4; j++) m1v[j] = 0ULL;
    #pragma unroll
    for (int j = 0; j < 2; j++) m2v[j] = 0ULL;
    float m3 = 0.0f;

    const float*  xbase = x + (size_t)e * DD;
    const size_t  xstep = (size_t)BB * DD;
    const int     base_lane = lane & 28;   // first lane of this element's 4-thread group

    #pragma unroll 1
    for (int t = 0; t < TT; t++) {
        // ---- load x_t (this element's 64 inputs; group-of-4 lanes dedup) ----
        const float4* xp = (const float4*)(xbase + (size_t)t * xstep);
        float4 xr[16];
        #pragma unroll
        for (int i = 0; i < 16; i++) xr[i] = xp[i];

        // ---- prefetch next timestep's x row into L2 (4 threads cover 256B) ----
        if (t + 1 < TT) {
            const char* pf = (const char*)(xbase + (size_t)(t + 1) * xstep) + q * 64;
            asm volatile("prefetch.global.L2 [%0];" :: "l"(pf));
        }

        // ============ layer 1: serial ascending-k FMA chains, 7 owned neurons ========
        ull_t acc[4];
        #pragma unroll
        for (int j = 0; j < 4; j++) acc[j] = 0ULL;

        #pragma unroll
        for (int i8 = 0; i8 < 16; i8++) {
            float xv[4] = {xr[i8].x, xr[i8].y, xr[i8].z, xr[i8].w};
            #pragma unroll
            for (int c = 0; c < 4; c++) {
                const int k = i8 * 4 + c;
                ull_t xx = pk2(xv[c], xv[c]);
                const ulonglong2* wr = (const ulonglong2*)(w1r + (size_t)k * 16 + q * 4);
                ulonglong2 wa = wr[0], wb = wr[1];
                acc[0] = fma2(xx, wa.x, acc[0]);
                acc[1] = fma2(xx, wa.y, acc[1]);
                acc[2] = fma2(xx, wb.x, acc[2]);
                acc[3] = fma2(xx, wb.y, acc[3]);
            }
        }

        // ============ LIF layer 1 (exact rounding sequence) ==========================
        ull_t sown[4];
        #pragma unroll
        for (int j = 0; j < 4; j++) {
            ull_t mold = m1v[j];
            float mlo, mhi;
            upk2(mold, mlo, mhi);
            float rlo = (mlo > 1.0f) ? 1.0f : 0.0f;
            float rhi = (mhi > 1.0f) ? 1.0f : 0.0f;
            ull_t cur = add2(acc[j], b1own[j]);           // dot + bias (separate round)
            ull_t mb  = mul2(BETA2, mold);                // RN(b*m)
            ull_t tmp = add2(mb, cur);                    // RN(.. + cur)
            ull_t mn  = fma2(pk2(rlo, rhi), NEG2, tmp);   // RN(.. - reset), exact product
            m1v[j] = mn;
            float nlo, nhi;
            upk2(mn, nlo, nhi);
            sown[j] = pk2((nlo > 1.0f) ? 1.0f : 0.0f,
                          (nhi > 1.0f) ? 1.0f : 0.0f);
        }

        // ---- all-gather s1 across the 4-thread group (spikes are exact {0,1}) ----
        ull_t g1[16];
        #pragma unroll
        for (int s = 0; s < 4; s++) {
            #pragma unroll
            for (int j = 0; j < 4; j++)
                g1[s * 4 + j] = __shfl_sync(0xFFFFFFFFu, sown[j], base_lane + s);
        }

        // ============ layer 2: serial ascending-i chains, owned h2 neurons ===========
        ull_t a2[2];
        a2[0] = 0ULL; a2[1] = 0ULL;
        #pragma unroll
        for (int i = 0; i < HH1; i++) {
            // h1 neuron i lives at group slot 4*(i/7) + (i%7)/2, lane (i%7)&1
            const int slot = 4 * (i / 7) + ((i % 7) >> 1);
            const int hsel = (i % 7) & 1;
            float s = getlane(g1[slot], hsel);
            ull_t ss = pk2(s, s);
            const ulonglong2* wr = (const ulonglong2*)(w2r + (size_t)i * 8 + q * 2);
            ulonglong2 u = wr[0];
            a2[0] = fma2(ss, u.x, a2[0]);
            a2[1] = fma2(ss, u.y, a2[1]);
        }

        // ============ LIF layer 2 ====================================================
        ull_t s2own[2];
        #pragma unroll
        for (int j = 0; j < 2; j++) {
            ull_t mold = m2v[j];
            float mlo, mhi;
            upk2(mold, mlo, mhi);
            float rlo = (mlo > 1.0f) ? 1.0f : 0.0f;
            float rhi = (mhi > 1.0f) ? 1.0f : 0.0f;
            ull_t cur = add2(a2[j], b2own[j]);
            ull_t mb  = mul2(BETA2, mold);
            ull_t tmp = add2(mb, cur);
            ull_t mn  = fma2(pk2(rlo, rhi), NEG2, tmp);
            m2v[j] = mn;
            float nlo, nhi;
            upk2(mn, nlo, nhi);
            s2own[j] = pk2((nlo > 1.0f) ? 1.0f : 0.0f,
                           (nhi > 1.0f) ? 1.0f : 0.0f);
        }

        // ---- all-gather s2 ----
        ull_t g2[8];
        #pragma unroll
        for (int s = 0; s < 4; s++) {
            #pragma unroll
            for (int j = 0; j < 2; j++)
                g2[s * 2 + j] = __shfl_sync(0xFFFFFFFFu, s2own[j], base_lane + s);
        }

        // ============ layer 3 + LIF 3 (serial chain, separate rounds) ================
        // h2 neuron n -> g2 slot/lane (split 4/4/3/3, pads skipped):
        float c3 = 0.0f;
        #pragma unroll
        for (int n = 0; n < HH2; n++) {
            const int slot = (n < 8) ? (n >> 1)
                           : (n < 11) ? (4 + ((n - 8) >> 1))
                                      : (6 + ((n - 11) >> 1));
            const int hsel = (n < 8) ? (n & 1)
                           : (n < 11) ? ((n - 8) & 1)
                                      : ((n - 11) & 1);
            float s = getlane(g2[slot], hsel);
            c3 = fmaf(s, w3s[n], c3);
        }
        float cur3 = __fadd_rn(c3, b3s);

        float r3  = (m3 > 1.0f) ? 1.0f : 0.0f;
        float mb3 = __fmul_rn(0.9f, m3);
        float t3  = __fadd_rn(mb3, cur3);
        m3 = __fsub_rn(t3, r3);

        if (q == 0) out[(size_t)t * BB + e] = m3;
    }
}

extern "C" void kernel_launch(void* const* d_in, const int* in_sizes, int n_in,
                              void* d_out, int out_size) {
    const float* x  = (const float*)d_in[0];
    const float* W1 = (const float*)d_in[1];
    const float* b1 = (const float*)d_in[2];
    const float* W2 = (const float*)d_in[3];
    const float* b2 = (const float*)d_in[4];
    const float* W3 = (const float*)d_in[5];
    const float* b3 = (const float*)d_in[6];
    float* out = (float*)d_out;

    // 8192 elements, 16 per block (64 threads = 4 threads per element)
    snn_fused_kernel<<<512, 64>>>(x, W1, b1, W2, b2, W3, b3, out);
}

// round 8
// speedup vs baseline: 1.1274x; 1.1274x over previous
#include <cuda_runtime.h>

// EthanolSNN: 3-layer LIF SNN inference. T=256, B=8192, D=64, H1=28, H2=14.
// Output mem3 [T, B, 1] fp32.
//
// Numerics: BIT-IDENTICAL to the round-5 passing kernel (rel_err 7.44e-4):
//  - every dot product: single serial ascending-index FMA chain per neuron
//    (spike-gated terms realized as predicated adds: fma(s,w,a) with s in {0,1}
//     is exactly add(a,w) when s=1 and exactly a when s=0)
//  - bias added as separate rounded add after the chain
//  - LIF: RN(RN(RN(b*m)+cur)-reset), reset subtract via exact-product fma
//  - threshold m>1 == (m-1)>0 in fp32
//
// Parallelization: 2 threads/element, neuron-split (round-5 structure).
// NEW: software pipelining across timesteps — layer-1 accumulation for step
// t+1 is computed inside step t's body, between the s1 spike exchange and the
// serial layer-2/3 tail, so its 448 fma2 + 256 LDS fill the tail's stalls.
// Spike exchange is 2 scalar bitmask shuffles (was 11 x 64-bit shuffles).

typedef unsigned long long ull_t;

#define TT 256
#define BB 8192
#define DD 64
#define HH1 28
#define HH2 14

__device__ __forceinline__ ull_t pk2(float lo, float hi) {
    ull_t r;
    asm("mov.b64 %0, {%1, %2};" : "=l"(r) : "f"(lo), "f"(hi));
    return r;
}
__device__ __forceinline__ void upk2(ull_t v, float& lo, float& hi) {
    asm("mov.b64 {%0, %1}, %2;" : "=f"(lo), "=f"(hi) : "l"(v));
}
__device__ __forceinline__ ull_t fma2(ull_t a, ull_t b, ull_t c) {
    ull_t d;
    asm("fma.rn.f32x2 %0, %1, %2, %3;" : "=l"(d) : "l"(a), "l"(b), "l"(c));
    return d;
}
__device__ __forceinline__ ull_t add2(ull_t a, ull_t b) {
    ull_t d;
    asm("add.rn.f32x2 %0, %1, %2;" : "=l"(d) : "l"(a), "l"(b));
    return d;
}
__device__ __forceinline__ ull_t mul2(ull_t a, ull_t b) {
    ull_t d;
    asm("mul.rn.f32x2 %0, %1, %2;" : "=l"(d) : "l"(a), "l"(b));
    return d;
}

__global__ void __launch_bounds__(64, 1)
snn_fused_kernel(const float* __restrict__ x,
                 const float* __restrict__ W1, const float* __restrict__ b1,
                 const float* __restrict__ W2, const float* __restrict__ b2,
                 const float* __restrict__ W3, const float* __restrict__ b3,
                 float* __restrict__ out)
{
    // w1p[k][qq*8+j] = {W1[qq*14+2j][k], W1[qq*14+2j+1][k]}  (row 16 ull = 128B)
    // w2p[i][qq*4+m] = {W2[7qq+2m][i],   W2[7qq+2m+1][i]}    (row 8 ull; m=3 hi pad)
    __shared__ __align__(16) ull_t w1p[DD * 16];
    __shared__ __align__(16) ull_t w2p[HH1 * 8];
    __shared__ ull_t b1p[14];
    __shared__ ull_t b2p[8];
    __shared__ float w3s[14];
    __shared__ float b3s;

    const int tid  = threadIdx.x;
    const int lane = tid & 31;
    const int warp = tid >> 5;
    const int p    = lane >> 1;            // element slot within warp (0..15)
    const int q    = lane & 1;             // neuron-half owner
    const int e    = blockIdx.x * 32 + warp * 16 + p;

    // ---- pack weights into shared (identical to round 5) ----
    for (int idx = tid; idx < DD * 16; idx += 64) {
        int k = idx >> 4, r = idx & 15, qq = r >> 3, j = r & 7;
        float lo = 0.f, hi = 0.f;
        if (j < 7) {
            lo = W1[(qq * 14 + 2 * j)     * DD + k];
            hi = W1[(qq * 14 + 2 * j + 1) * DD + k];
        }
        w1p[idx] = pk2(lo, hi);
    }
    for (int idx = tid; idx < HH1 * 8; idx += 64) {
        int i = idx >> 3, r = idx & 7, qq = r >> 2, m = r & 3;
        float lo = (2 * m     < 7) ? W2[(qq * 7 + 2 * m)     * HH1 + i] : 0.f;
        float hi = (2 * m + 1 < 7) ? W2[(qq * 7 + 2 * m + 1) * HH1 + i] : 0.f;
        w2p[idx] = pk2(lo, hi);
    }
    if (tid < 14) {
        int qq = tid / 7, ii = tid - qq * 7;
        b1p[tid] = pk2(b1[qq * 14 + 2 * ii], b1[qq * 14 + 2 * ii + 1]);
        w3s[tid] = W3[tid];
    }
    if (tid < 8) {
        int qq = tid >> 2, m = tid & 3;
        float lo = (2 * m     < 7) ? b2[qq * 7 + 2 * m]     : 0.f;
        float hi = (2 * m + 1 < 7) ? b2[qq * 7 + 2 * m + 1] : 0.f;
        b2p[tid] = pk2(lo, hi);
    }
    if (tid == 0) b3s = b3[0];
    __syncthreads();

    const ull_t* w1q = w1p + q * 8;    // this thread's neuron-half weight columns

    ull_t b1own[7], b2own[4];
    #pragma unroll
    for (int i = 0; i < 7; i++) b1own[i] = b1p[q * 7 + i];
    #pragma unroll
    for (int m = 0; m < 4; m++) b2own[m] = b2p[q * 4 + m];

    const ull_t BETA2 = pk2(0.9f, 0.9f);
    const ull_t NEG2  = pk2(-1.0f, -1.0f);

    ull_t m1v[7], m2v[4];
    #pragma unroll
    for (int i = 0; i < 7; i++) m1v[i] = 0ULL;
    #pragma unroll
    for (int m = 0; m < 4; m++) m2v[m] = 0ULL;
    float m3 = 0.0f;

    const float*  xbase = x + (size_t)e * DD;
    const size_t  xstep = (size_t)BB * DD;

    // ================= prologue: layer-1 accumulation for t=0 =================
    ull_t acc[7];
    {
        const float4* xp = (const float4*)xbase;
        float4 xr[16];
        #pragma unroll
        for (int i = 0; i < 16; i++) xr[i] = xp[i];
        #pragma unroll
        for (int j = 0; j < 7; j++) acc[j] = 0ULL;
        #pragma unroll
        for (int i8 = 0; i8 < 16; i8++) {
            float xv[4] = {xr[i8].x, xr[i8].y, xr[i8].z, xr[i8].w};
            #pragma unroll
            for (int c = 0; c < 4; c++) {
                const int k = i8 * 4 + c;
                ull_t xx = pk2(xv[c], xv[c]);
                const ulonglong2* wr = (const ulonglong2*)(w1q + (size_t)k * 16);
                ulonglong2 wa = wr[0], wb = wr[1], wc = wr[2];
                ull_t w7 = (w1q + (size_t)k * 16)[6];
                acc[0] = fma2(xx, wa.x, acc[0]);
                acc[1] = fma2(xx, wa.y, acc[1]);
                acc[2] = fma2(xx, wb.x, acc[2]);
                acc[3] = fma2(xx, wc.x, acc[3]);   // note: order of regs below
                acc[4] = fma2(xx, wb.y, acc[4]);
                acc[5] = fma2(xx, wc.y, acc[5]);
                acc[6] = fma2(xx, w7,   acc[6]);
            }
        }
        // fix accumulator<->neuron mapping back to canonical order:
        // (acc[j] must be neuron pair j; above wb.y is pair 3, wc.x is pair 4)
        ull_t t3 = acc[3], t4 = acc[4];
        acc[3] = t4; acc[4] = t3;
    }

    #pragma unroll 1
    for (int t = 0; t < TT; t++) {
        // ---- (1) issue next-x loads early (consumed by the accn block) ----
        const int tn = (t + 1 < TT) ? (t + 1) : t;
        const float4* xp = (const float4*)(xbase + (size_t)tn * xstep);
        float4 xn[16];
        #pragma unroll
        for (int i = 0; i < 16; i++) xn[i] = xp[i];

        if (t + 2 < TT) {
            const char* pf = (const char*)(xbase + (size_t)(t + 2) * xstep) + q * 128;
            asm volatile("prefetch.global.L2 [%0];" :: "l"(pf));
        }

        // ---- (2) LIF layer 1 (exact rounding sequence) + spike bitmask ----
        unsigned own14 = 0u;
        #pragma unroll
        for (int j = 0; j < 7; j++) {
            ull_t mold = m1v[j];
            float mlo, mhi;
            upk2(mold, mlo, mhi);
            float rlo = (mlo > 1.0f) ? 1.0f : 0.0f;
            float rhi = (mhi > 1.0f) ? 1.0f : 0.0f;
            ull_t cur = add2(acc[j], b1own[j]);           // dot + bias (separate round)
            ull_t mb  = mul2(BETA2, mold);                // RN(b*m)
            ull_t tmp = add2(mb, cur);                    // RN(.. + cur)
            ull_t mn  = fma2(pk2(rlo, rhi), NEG2, tmp);   // RN(.. - reset), exact product
            m1v[j] = mn;
            float nlo, nhi;
            upk2(mn, nlo, nhi);
            own14 |= (nlo > 1.0f) ? (1u << (2 * j))     : 0u;
            own14 |= (nhi > 1.0f) ? (1u << (2 * j + 1)) : 0u;
        }
        unsigned oth14  = __shfl_xor_sync(0xFFFFFFFFu, own14, 1);
        unsigned full28 = q ? (oth14 | (own14 << 14)) : (own14 | (oth14 << 14));

        // ---- (3) layer-1 accumulation for step t+1 (fills tail stalls) ----
        ull_t accn[7];
        #pragma unroll
        for (int j = 0; j < 7; j++) accn[j] = 0ULL;
        #pragma unroll
        for (int i8 = 0; i8 < 16; i8++) {
            float xv[4] = {xn[i8].x, xn[i8].y, xn[i8].z, xn[i8].w};
            #pragma unroll
            for (int c = 0; c < 4; c++) {
                const int k = i8 * 4 + c;
                ull_t xx = pk2(xv[c], xv[c]);
                const ulonglong2* wr = (const ulonglong2*)(w1q + (size_t)k * 16);
                ulonglong2 wa = wr[0], wb = wr[1], wc = wr[2];
                ull_t w7 = (w1q + (size_t)k * 16)[6];
                accn[0] = fma2(xx, wa.x, accn[0]);
                accn[1] = fma2(xx, wa.y, accn[1]);
                accn[2] = fma2(xx, wb.x, accn[2]);
                accn[3] = fma2(xx, wb.y, accn[3]);
                accn[4] = fma2(xx, wc.x, accn[4]);
                accn[5] = fma2(xx, wc.y, accn[5]);
                accn[6] = fma2(xx, w7,   accn[6]);
            }
        }

        // ---- (4) layer 2: spike-predicated adds (bit-identical to fma chain) ----
        ull_t a2[4];
        #pragma unroll
        for (int m = 0; m < 4; m++) a2[m] = 0ULL;
        #pragma unroll
        for (int i = 0; i < HH1; i++) {
            const ulonglong2* wr = (const ulonglong2*)(w2p + (size_t)i * 8 + q * 4);
            ulonglong2 u0 = wr[0], u1 = wr[1];
            if (full28 & (1u << i)) {
                a2[0] = add2(a2[0], u0.x);
                a2[1] = add2(a2[1], u0.y);
                a2[2] = add2(a2[2], u1.x);
                a2[3] = add2(a2[3], u1.y);
            }
        }

        // ---- (5) LIF layer 2 + spike bitmask ----
        unsigned own7 = 0u;
        #pragma unroll
        for (int m = 0; m < 4; m++) {
            ull_t mold = m2v[m];
            float mlo, mhi;
            upk2(mold, mlo, mhi);
            float rlo = (mlo > 1.0f) ? 1.0f : 0.0f;
            float rhi = (mhi > 1.0f) ? 1.0f : 0.0f;
            ull_t cur = add2(a2[m], b2own[m]);
            ull_t mb  = mul2(BETA2, mold);
            ull_t tmp = add2(mb, cur);
            ull_t mn  = fma2(pk2(rlo, rhi), NEG2, tmp);
            m2v[m] = mn;
            float nlo, nhi;
            upk2(mn, nlo, nhi);
            own7 |= (nlo > 1.0f) ? (1u << (2 * m)) : 0u;
            if (2 * m + 1 < 7)                       // static: skip pad lane
                own7 |= (nhi > 1.0f) ? (1u << (2 * m + 1)) : 0u;
        }
        unsigned oth7   = __shfl_xor_sync(0xFFFFFFFFu, own7, 1);
        unsigned full14 = q ? (oth7 | (own7 << 7)) : (own7 | (oth7 << 7));

        // ---- (6) layer 3 (predicated adds) + LIF 3 ----
        float c3 = 0.0f;
        #pragma unroll
        for (int n = 0; n < HH2; n++) {
            if (full14 & (1u << n)) c3 = __fadd_rn(c3, w3s[n]);
        }
        float cur3 = __fadd_rn(c3, b3s);

        float r3  = (m3 > 1.0f) ? 1.0f : 0.0f;
        float mb3 = __fmul_rn(0.9f, m3);
        float t3  = __fadd_rn(mb3, cur3);
        m3 = __fsub_rn(t3, r3);

        if (q == 0) out[(size_t)t * BB + e] = m3;

        // ---- (7) rotate pipelined accumulators ----
        #pragma unroll
        for (int j = 0; j < 7; j++) acc[j] = accn[j];
    }
}

extern "C" void kernel_launch(void* const* d_in, const int* in_sizes, int n_in,
                              void* d_out, int out_size) {
    const float* x  = (const float*)d_in[0];
    const float* W1 = (const float*)d_in[1];
    const float* b1 = (const float*)d_in[2];
    const float* W2 = (const float*)d_in[3];
    const float* b2 = (const float*)d_in[4];
    const float* W3 = (const float*)d_in[5];
    const float* b3 = (const float*)d_in[6];
    float* out = (float*)d_out;

    // 8192 elements, 32 per block (64 threads = 2 threads per element)
    snn_fused_kernel<<<256, 64>>>(x, W1, b1, W2, b2, W3, b3, out);
}

// round 10
// speedup vs baseline: 1.5135x; 1.3424x over previous
#include <cuda_runtime.h>

// EthanolSNN: 3-layer LIF SNN inference. T=256, B=8192, D=64, H1=28, H2=14.
// Output mem3 [T, B, 1] fp32.
//
// Two-kernel split:
//  K1: layer-1 accumulations for ALL (t,e) at full occupancy (no recurrence).
//      Serial ascending-k fma2 chains, bit-identical to the round-5 kernel.
//      Raw (pre-bias) accumulators stored exactly to __device__ scratch.
//  K2: sequential LIF recurrence (round-5 tail, unchanged numerics), reading
//      the precomputed layer-1 currents.
//
// Numerics BIT-IDENTICAL to round-5 passing kernel (rel_err 7.44e-4):
//  - dot products: single serial ascending-index FMA chain per neuron
//  - bias added as separate rounded add after the chain
//  - LIF: RN(RN(RN(b*m)+cur)-reset), reset subtract via exact-product fma
//  - threshold m>1 == (m-1)>0 in fp32

typedef unsigned long long ull_t;

#define TT 256
#define BB 8192
#define DD 64
#define HH1 28
#define HH2 14

// scratch: [et][16] ull; et = t*BB+e; thread half q uses slots [q*8 .. q*8+6]
#define SCRATCH_ULLS (256ULL * 8192ULL * 16ULL)
__device__ ull_t g_cur1[SCRATCH_ULLS];   // 268 MB, module-load allocated

__device__ __forceinline__ ull_t pk2(float lo, float hi) {
    ull_t r;
    asm("mov.b64 %0, {%1, %2};" : "=l"(r) : "f"(lo), "f"(hi));
    return r;
}
__device__ __forceinline__ void upk2(ull_t v, float& lo, float& hi) {
    asm("mov.b64 {%0, %1}, %2;" : "=f"(lo), "=f"(hi) : "l"(v));
}
__device__ __forceinline__ ull_t fma2(ull_t a, ull_t b, ull_t c) {
    ull_t d;
    asm("fma.rn.f32x2 %0, %1, %2, %3;" : "=l"(d) : "l"(a), "l"(b), "l"(c));
    return d;
}
__device__ __forceinline__ ull_t add2(ull_t a, ull_t b) {
    ull_t d;
    asm("add.rn.f32x2 %0, %1, %2;" : "=l"(d) : "l"(a), "l"(b));
    return d;
}
__device__ __forceinline__ ull_t mul2(ull_t a, ull_t b) {
    ull_t d;
    asm("mul.rn.f32x2 %0, %1, %2;" : "=l"(d) : "l"(a), "l"(b));
    return d;
}

// ============================================================================
// Kernel 1: layer-1 accumulation, all (t,e), full occupancy.
// 128 threads/block; thread = (slot s = tid>>1, half q = tid&1); each thread
// computes BOTH neuron-half chains for 2 consecutive element-timesteps.
// ============================================================================
__global__ void __launch_bounds__(128)
snn_layer1_kernel(const float* __restrict__ x, const float* __restrict__ W1)
{
    // w1p[k][qq*8+j] = {W1[qq*14+2j][k], W1[qq*14+2j+1][k]}  (row 16 ull = 128B)
    __shared__ __align__(16) ull_t w1p[DD * 16];

    const int tid = threadIdx.x;
    for (int idx = tid; idx < DD * 16; idx += 128) {
        int k = idx >> 4, r = idx & 15, qq = r >> 3, j = r & 7;
        float lo = 0.f, hi = 0.f;
        if (j < 7) {
            lo = W1[(qq * 14 + 2 * j)     * DD + k];
            hi = W1[(qq * 14 + 2 * j + 1) * DD + k];
        }
        w1p[idx] = pk2(lo, hi);
    }
    __syncthreads();

    const int q = tid & 1;
    const int s = tid >> 1;                       // 0..63
    const size_t et0 = (size_t)blockIdx.x * 128 + (size_t)s * 2;  // et0, et0+1

    const ull_t* w1q = w1p + q * 8;

    ull_t a0[7], a1[7];
    #pragma unroll
    for (int j = 0; j < 7; j++) { a0[j] = 0ULL; a1[j] = 0ULL; }

    const float4* xA = (const float4*)(x + et0 * DD);
    const float4* xB = (const float4*)(x + (et0 + 1) * DD);

    #pragma unroll
    for (int i8 = 0; i8 < 16; i8++) {
        float4 va = __ldcs(xA + i8);
        float4 vb = __ldcs(xB + i8);
        float av[4] = {va.x, va.y, va.z, va.w};
        float bv[4] = {vb.x, vb.y, vb.z, vb.w};
        #pragma unroll
        for (int c = 0; c < 4; c++) {
            const int k = i8 * 4 + c;
            const ulonglong2* wr = (const ulonglong2*)(w1q + (size_t)k * 16);
            ulonglong2 wa = wr[0], wb = wr[1], wc = wr[2];
            ull_t w7 = (w1q + (size_t)k * 16)[6];
            ull_t xa = pk2(av[c], av[c]);
            ull_t xb = pk2(bv[c], bv[c]);
            a0[0] = fma2(xa, wa.x, a0[0]);  a1[0] = fma2(xb, wa.x, a1[0]);
            a0[1] = fma2(xa, wa.y, a0[1]);  a1[1] = fma2(xb, wa.y, a1[1]);
            a0[2] = fma2(xa, wb.x, a0[2]);  a1[2] = fma2(xb, wb.x, a1[2]);
            a0[3] = fma2(xa, wb.y, a0[3]);  a1[3] = fma2(xb, wb.y, a1[3]);
            a0[4] = fma2(xa, wc.x, a0[4]);  a1[4] = fma2(xb, wc.x, a1[4]);
            a0[5] = fma2(xa, wc.y, a0[5]);  a1[5] = fma2(xb, wc.y, a1[5]);
            a0[6] = fma2(xa, w7,   a0[6]);  a1[6] = fma2(xb, w7,   a1[6]);
        }
    }

    // store (exact, unrounded) — 4x STG.128 per et-half
    ulonglong2* d0 = (ulonglong2*)(g_cur1 + et0 * 16 + q * 8);
    ulonglong2* d1 = (ulonglong2*)(g_cur1 + (et0 + 1) * 16 + q * 8);
    ulonglong2 p;
    p.x = a0[0]; p.y = a0[1]; d0[0] = p;
    p.x = a0[2]; p.y = a0[3]; d0[1] = p;
    p.x = a0[4]; p.y = a0[5]; d0[2] = p;
    p.x = a0[6]; p.y = 0ULL;  d0[3] = p;
    p.x = a1[0]; p.y = a1[1]; d1[0] = p;
    p.x = a1[2]; p.y = a1[3]; d1[1] = p;
    p.x = a1[4]; p.y = a1[5]; d1[2] = p;
    p.x = a1[6]; p.y = 0ULL;  d1[3] = p;
}

// ============================================================================
// Kernel 2: LIF recurrence (round-5 tail, numerics unchanged).
// 2 threads/element, neuron-split; 64 threads/block, 256 blocks.
// ============================================================================
__global__ void __launch_bounds__(64, 1)
snn_recur_kernel(const float* __restrict__ b1,
                 const float* __restrict__ W2, const float* __restrict__ b2,
                 const float* __restrict__ W3, const float* __restrict__ b3,
                 float* __restrict__ out)
{
    // w2p[i][qq*4+m] = {W2[7qq+2m][i], W2[7qq+2m+1][i]}  (row 8 ull; m=3 hi pad)
    __shared__ __align__(16) ull_t w2p[HH1 * 8];
    __shared__ ull_t b1p[14];
    __shared__ ull_t b2p[8];
    __shared__ float w3s[14];
    __shared__ float b3s;

    const int tid  = threadIdx.x;
    const int lane = tid & 31;
    const int warp = tid >> 5;
    const int p    = lane >> 1;            // element slot within warp (0..15)
    const int q    = lane & 1;             // neuron-half owner
    const int e    = blockIdx.x * 32 + warp * 16 + p;

    for (int idx = tid; idx < HH1 * 8; idx += 64) {
        int i = idx >> 3, r = idx & 7, qq = r >> 2, m = r & 3;
        float lo = (2 * m     < 7) ? W2[(qq * 7 + 2 * m)     * HH1 + i] : 0.f;
        float hi = (2 * m + 1 < 7) ? W2[(qq * 7 + 2 * m + 1) * HH1 + i] : 0.f;
        w2p[idx] = pk2(lo, hi);
    }
    if (tid < 14) {
        int qq = tid / 7, ii = tid - qq * 7;
        b1p[tid] = pk2(b1[qq * 14 + 2 * ii], b1[qq * 14 + 2 * ii + 1]);
        w3s[tid] = W3[tid];
    }
    if (tid < 8) {
        int qq = tid >> 2, m = tid & 3;
        float lo = (2 * m     < 7) ? b2[qq * 7 + 2 * m]     : 0.f;
        float hi = (2 * m + 1 < 7) ? b2[qq * 7 + 2 * m + 1] : 0.f;
        b2p[tid] = pk2(lo, hi);
    }
    if (tid == 0) b3s = b3[0];
    __syncthreads();

    ull_t b1own[7], b2own[4];
    #pragma unroll
    for (int i = 0; i < 7; i++) b1own[i] = b1p[q * 7 + i];
    #pragma unroll
    for (int m = 0; m < 4; m++) b2own[m] = b2p[q * 4 + m];

    const ull_t BETA2 = pk2(0.9f, 0.9f);
    const ull_t NEG2  = pk2(-1.0f, -1.0f);

    ull_t m1v[7], m2v[4];
    #pragma unroll
    for (int i = 0; i < 7; i++) m1v[i] = 0ULL;
    #pragma unroll
    for (int m = 0; m < 4; m++) m2v[m] = 0ULL;
    float m3 = 0.0f;

    const ull_t* cbase = g_cur1 + (size_t)e * 16 + q * 8;
    const size_t cstep = (size_t)BB * 16;

    #pragma unroll 1
    for (int t = 0; t < TT; t++) {
        // ---- load this step's layer-1 accumulators (4x LDG.128) ----
        const ulonglong2* cp = (const ulonglong2*)(cbase + (size_t)t * cstep);
        ulonglong2 c0 = cp[0], c1 = cp[1], c2 = cp[2], c3v = cp[3];
        ull_t acc[7] = {c0.x, c0.y, c1.x, c1.y, c2.x, c2.y, c3v.x};

        // ---- prefetch next step's accumulators into L2 ----
        if (t + 1 < TT) {
            const char* pf = (const char*)(cbase + (size_t)(t + 1) * cstep);
            asm volatile("prefetch.global.L2 [%0];" :: "l"(pf));
        }

        // ---- LIF layer 1 (exact rounding sequence) ----
        float s1own[14];
        #pragma unroll
        for (int i = 0; i < 7; i++) {
            ull_t mold = m1v[i];
            float mlo, mhi;
            upk2(mold, mlo, mhi);
            float rlo = (mlo > 1.0f) ? 1.0f : 0.0f;
            float rhi = (mhi > 1.0f) ? 1.0f : 0.0f;
            ull_t cur = add2(acc[i], b1own[i]);           // dot + bias (separate round)
            ull_t mb  = mul2(BETA2, mold);                // RN(b*m)
            ull_t tmp = add2(mb, cur);                    // RN(.. + cur)
            ull_t mn  = fma2(pk2(rlo, rhi), NEG2, tmp);   // RN(.. - reset), exact product
            m1v[i] = mn;
            float nlo, nhi;
            upk2(mn, nlo, nhi);
            s1own[2 * i]     = (nlo > 1.0f) ? 1.0f : 0.0f;
            s1own[2 * i + 1] = (nhi > 1.0f) ? 1.0f : 0.0f;
        }

        // ---- exchange spike halves across the pair ----
        float s1o[14];
        #pragma unroll
        for (int i = 0; i < 7; i++) {
            ull_t sp = pk2(s1own[2 * i], s1own[2 * i + 1]);
            ull_t g  = __shfl_xor_sync(0xFFFFFFFFu, sp, 1);
            upk2(g, s1o[2 * i], s1o[2 * i + 1]);
        }
        float s1all[28];
        #pragma unroll
        for (int i = 0; i < 14; i++) {
            s1all[i]      = q ? s1o[i]   : s1own[i];
            s1all[14 + i] = q ? s1own[i] : s1o[i];
        }

        // ---- layer 2: serial ascending-i FMA chains, 7 owned h2 neurons ----
        ull_t a2[4];
        #pragma unroll
        for (int m = 0; m < 4; m++) a2[m] = 0ULL;
        #pragma unroll
        for (int i = 0; i < HH1; i++) {
            ull_t ss = pk2(s1all[i], s1all[i]);
            const ulonglong2* wr = (const ulonglong2*)(w2p + (size_t)i * 8 + q * 4);
            ulonglong2 u0 = wr[0], u1 = wr[1];
            a2[0] = fma2(ss, u0.x, a2[0]);
            a2[1] = fma2(ss, u0.y, a2[1]);
            a2[2] = fma2(ss, u1.x, a2[2]);
            a2[3] = fma2(ss, u1.y, a2[3]);
        }

        // ---- LIF layer 2 ----
        float s2own[8];
        #pragma unroll
        for (int m = 0; m < 4; m++) {
            ull_t mold = m2v[m];
            float mlo, mhi;
            upk2(mold, mlo, mhi);
            float rlo = (mlo > 1.0f) ? 1.0f : 0.0f;
            float rhi = (mhi > 1.0f) ? 1.0f : 0.0f;
            ull_t cur = add2(a2[m], b2own[m]);
            ull_t mb  = mul2(BETA2, mold);
            ull_t tmp = add2(mb, cur);
            ull_t mn  = fma2(pk2(rlo, rhi), NEG2, tmp);
            m2v[m] = mn;
            float nlo, nhi;
            upk2(mn, nlo, nhi);
            s2own[2 * m]     = (nlo > 1.0f) ? 1.0f : 0.0f;
            s2own[2 * m + 1] = (nhi > 1.0f) ? 1.0f : 0.0f;
        }

        // ---- exchange s2 halves ----
        float s2o[8];
        #pragma unroll
        for (int m = 0; m < 4; m++) {
            ull_t sp = pk2(s2own[2 * m], s2own[2 * m + 1]);
            ull_t g  = __shfl_xor_sync(0xFFFFFFFFu, sp, 1);
            upk2(g, s2o[2 * m], s2o[2 * m + 1]);
        }
        float s2all[14];
        #pragma unroll
        for (int i = 0; i < 7; i++) {
            s2all[i]     = q ? s2o[i]   : s2own[i];
            s2all[7 + i] = q ? s2own[i] : s2o[i];
        }

        // ---- layer 3 + LIF 3 (serial chain, separate rounds) ----
        float c3 = 0.0f;
        #pragma unroll
        for (int i = 0; i < HH2; i++) c3 = fmaf(s2all[i], w3s[i], c3);
        float cur3 = __fadd_rn(c3, b3s);

        float r3  = (m3 > 1.0f) ? 1.0f : 0.0f;
        float mb3 = __fmul_rn(0.9f, m3);
        float t3  = __fadd_rn(mb3, cur3);
        m3 = __fsub_rn(t3, r3);

        if (q == 0) out[(size_t)t * BB + e] = m3;
    }
}

extern "C" void kernel_launch(void* const* d_in, const int* in_sizes, int n_in,
                              void* d_out, int out_size) {
    const float* x  = (const float*)d_in[0];
    const float* W1 = (const float*)d_in[1];
    const float* b1 = (const float*)d_in[2];
    const float* W2 = (const float*)d_in[3];
    const float* b2 = (const float*)d_in[4];
    const float* W3 = (const float*)d_in[5];
    const float* b3 = (const float*)d_in[6];
    float* out = (float*)d_out;

    // K1: 2,097,152 element-timesteps; 2 per thread, 2 half-threads each
    // -> 2,097,152 threads = 16384 blocks x 128
    snn_layer1_kernel<<<16384, 128>>>(x, W1);

    // K2: 8192 elements, 32 per block (64 threads = 2 threads per element)
    snn_recur_kernel<<<256, 64>>>(b1, W2, b2, W3, b3, out);
}